// round 10
// baseline (speedup 1.0000x reference)
#include <cuda_runtime.h>
#include <cuda_fp16.h>
#include <math.h>
#include <stdint.h>

// ---------------- problem constants ----------------
#define B_   8
#define E_   8
#define C_   128
#define KW_  512
#define Mtot 16384          // B*L
#define KKd  4096           // KW*E
#define NNd  256            // 2*C

// ---------------- GEMM tiling ----------------
#define MT     64           // CTA M tile
#define KC     64           // K chunk (fp16 elems)
#define NCHUNK (KKd / KC)   // 64
#define NTH    512          // 16 warps: 2(M) x 8(N), warp tile 32x32
#define NCTA   (Mtot / MT)  // 256

// smem (bytes)
#define PITCH   144         // 64 fp16 data + 8 pad -> conflict-free 8-row ldmatrix groups
#define A_STG   (64 * PITCH)         // 9216 per stage
#define B_STG   (256 * PITCH)        // 36864 per stage
#define SM_A    0
#define SM_B    (2 * A_STG)          // 18432
#define SMEMSZ  (SM_B + 2 * B_STG)   // 92160
// epilogue v2 tile overlay: [64][132] floats = 33792 B (fits in pipe region)
#define VPITCH  132

// fp16 weights, [n][kk] K-major; n<128 -> W1, n>=128 -> W2
__device__ __half g_Bh[(size_t)NNd * KKd];

// ---------------- helpers ----------------
__device__ __forceinline__ uint32_t smem_u32(const void* p) {
    uint32_t a;
    asm("{ .reg .u64 t; cvta.to.shared.u64 t, %1; cvt.u32.u64 %0, t; }" : "=r"(a) : "l"(p));
    return a;
}
__device__ __forceinline__ uint32_t pack_h2(float x, float y) {
    __half2 t = __floats2half2_rn(x, y);
    return *reinterpret_cast<uint32_t*>(&t);
}
__device__ __forceinline__ void ldmx4(uint32_t* r, uint32_t addr) {
    asm volatile("ldmatrix.sync.aligned.m8n8.x4.shared.b16 {%0,%1,%2,%3}, [%4];"
                 : "=r"(r[0]), "=r"(r[1]), "=r"(r[2]), "=r"(r[3]) : "r"(addr));
}
__device__ __forceinline__ void mma16816(float* d, const uint32_t* a, uint32_t b0, uint32_t b1) {
    asm volatile("mma.sync.aligned.m16n8k16.row.col.f32.f16.f16.f32 "
                 "{%0,%1,%2,%3}, {%4,%5,%6,%7}, {%8,%9}, {%0,%1,%2,%3};"
                 : "+f"(d[0]), "+f"(d[1]), "+f"(d[2]), "+f"(d[3])
                 : "r"(a[0]), "r"(a[1]), "r"(a[2]), "r"(a[3]), "r"(b0), "r"(b1));
}
__device__ __forceinline__ void sts64(uint32_t a, uint32_t x, uint32_t y) {
    asm volatile("st.shared.v2.b32 [%0], {%1,%2};" :: "r"(a), "r"(x), "r"(y) : "memory");
}
__device__ __forceinline__ void stsf2(uint32_t a, float x, float y) {
    asm volatile("st.shared.v2.f32 [%0], {%1,%2};" :: "r"(a), "f"(x), "f"(y) : "memory");
}
__device__ __forceinline__ void cpasync16(uint32_t dst, const void* src) {
    asm volatile("cp.async.cg.shared.global [%0], [%1], 16;" :: "r"(dst), "l"(src) : "memory");
}
__device__ __forceinline__ void cp_commit() { asm volatile("cp.async.commit_group;" ::: "memory"); }
__device__ __forceinline__ void cp_wait1() { asm volatile("cp.async.wait_group 1;" ::: "memory"); }
__device__ __forceinline__ void cp_wait0() { asm volatile("cp.async.wait_group 0;" ::: "memory"); }
__device__ __forceinline__ void atomicMaxFloat(float* addr, float val) {
    if (val >= 0.0f) atomicMax((int*)addr, __float_as_int(val));
    else             atomicMin((unsigned int*)addr, __float_as_uint(val));
}

// ---------------- prep: weights -> fp16 [n][kk], coalesced; also init out ----------------
__global__ void prep_weights(const float* __restrict__ W1, const float* __restrict__ W2,
                             float* __restrict__ out) {
    int idx = blockIdx.x * blockDim.x + threadIdx.x;   // over C_*KW_ = 65536
    if (idx < B_ * C_) out[idx] = -INFINITY;
    if (idx >= C_ * KW_) return;
    int c = idx / KW_;
    int k = idx % KW_;
    uint32_t p1[4], p2[4];
#pragma unroll
    for (int e2 = 0; e2 < 4; e2++) {
        float a0 = W1[((size_t)c * E_ + 2 * e2) * KW_ + k];
        float a1 = W1[((size_t)c * E_ + 2 * e2 + 1) * KW_ + k];
        p1[e2] = pack_h2(a0, a1);
        float b0 = W2[((size_t)c * E_ + 2 * e2) * KW_ + k];
        float b1v = W2[((size_t)c * E_ + 2 * e2 + 1) * KW_ + k];
        p2[e2] = pack_h2(b0, b1v);
    }
    *(uint4*)&g_Bh[(size_t)c * KKd + k * E_]        = make_uint4(p1[0], p1[1], p1[2], p1[3]);
    *(uint4*)&g_Bh[(size_t)(C_ + c) * KKd + k * E_] = make_uint4(p2[0], p2[1], p2[2], p2[3]);
}

// ---------------- main fused GEMM + gate + max ----------------
__global__ __launch_bounds__(NTH, 2)
void gemm_gate_max(const float* __restrict__ Z,
                   const float* __restrict__ b1,
                   const float* __restrict__ b2,
                   float* __restrict__ out) {
    extern __shared__ char smem[];
    const uint32_t sb = smem_u32(smem);
    const int tid  = threadIdx.x;
    const int wid  = tid >> 5;
    const int lane = tid & 31;
    const int wm   = wid & 1;        // M group (0..1), 32 rows each
    const int wn   = wid >> 1;       // N group (0..7), 32 cols each
    const int m_base = blockIdx.x * MT;

    const uint32_t fragBase = (uint32_t)((lane % 16) * PITCH + (lane / 16) * 16);
    const uint32_t wmOff = (uint32_t)(wm * 32 * PITCH);
    const uint32_t wnOff = (uint32_t)(wn * 32 * PITCH);

    // ---- A gmem/smem mapping: 2 float4 per thread per chunk (64 rows x 16 float4) ----
    const float* aSrc[2];
    uint32_t     aDst[2];
#pragma unroll
    for (int q = 0; q < 2; q++) {
        int i   = tid + q * 512;       // 0..1023
        int row = i >> 4;              // 0..63
        int f4  = i & 15;              // float4 index within row
        aSrc[q] = Z + (size_t)(m_base + row) * KKd + f4 * 4;
        aDst[q] = (uint32_t)(row * PITCH + f4 * 8);
    }
    // ---- B cp.async mapping: 4 granules (16B) per thread ----
    const __half* bSrc[4];
    uint32_t bDst[4];
#pragma unroll
    for (int q = 0; q < 4; q++) {
        int g  = tid + q * 512;        // 0..2047
        int n  = g >> 3;               // 0..255
        int ko = (g & 7) * 8;          // fp16 offset in row (0..56)
        bSrc[q] = g_Bh + (size_t)n * KKd + ko;
        bDst[q] = (uint32_t)(n * PITCH + ko * 2);
    }

    float acc[2][4][4];
#pragma unroll
    for (int mi = 0; mi < 2; mi++)
#pragma unroll
        for (int ni = 0; ni < 4; ni++)
#pragma unroll
            for (int q = 0; q < 4; q++) acc[mi][ni][q] = 0.0f;

    uint32_t pA[4];   // packed fp16 A prefetch (2 float4 -> 4 regs)

    // ---- prologue: chunk 0 ----
#pragma unroll
    for (int q = 0; q < 4; q++)
        cpasync16(sb + SM_B + bDst[q], bSrc[q]);
    cp_commit();
#pragma unroll
    for (int q = 0; q < 2; q++) {
        float4 v = *(const float4*)(aSrc[q]);
        sts64(sb + SM_A + aDst[q], pack_h2(v.x, v.y), pack_h2(v.z, v.w));
    }
#pragma unroll
    for (int q = 0; q < 2; q++) {
        float4 v = *(const float4*)(aSrc[q] + KC);
        pA[2 * q]     = pack_h2(v.x, v.y);
        pA[2 * q + 1] = pack_h2(v.z, v.w);
    }

    for (int j = 0; j < NCHUNK; ++j) {
        const uint32_t cur = j & 1;
        const uint32_t nxt = cur ^ 1;

        __syncthreads();   // chunk j-1 consumed -> safe to overwrite stage nxt

        if (j + 1 < NCHUNK) {
            const int ke = (j + 1) * KC;
#pragma unroll
            for (int q = 0; q < 4; q++)
                cpasync16(sb + SM_B + nxt * B_STG + bDst[q], bSrc[q] + ke);
            cp_commit();
            sts64(sb + SM_A + nxt * A_STG + aDst[0], pA[0], pA[1]);
            sts64(sb + SM_A + nxt * A_STG + aDst[1], pA[2], pA[3]);
            cp_wait1();
        } else {
            cp_wait0();
        }
        __syncthreads();   // stage cur fully visible

        if (j + 2 < NCHUNK) {
#pragma unroll
            for (int q = 0; q < 2; q++) {
                float4 v = *(const float4*)(aSrc[q] + (j + 2) * KC);
                pA[2 * q]     = pack_h2(v.x, v.y);
                pA[2 * q + 1] = pack_h2(v.z, v.w);
            }
        }

        // ---- compute chunk j: 4 k16 slices, single fp16 pass ----
        const uint32_t sA = sb + SM_A + cur * A_STG;
        const uint32_t sB = sb + SM_B + cur * B_STG;

#pragma unroll
        for (int ks = 0; ks < 4; ks++) {
            const uint32_t ko = ks * 32;
            uint32_t af[2][4], bf[2][4];
#pragma unroll
            for (int mi = 0; mi < 2; mi++)
                ldmx4(af[mi], sA + wmOff + mi * (16 * PITCH) + ko + fragBase);
#pragma unroll
            for (int n2 = 0; n2 < 2; n2++)
                ldmx4(bf[n2], sB + wnOff + n2 * (16 * PITCH) + ko + fragBase);
#pragma unroll
            for (int mi = 0; mi < 2; mi++)
#pragma unroll
                for (int ni = 0; ni < 4; ni++)
                    mma16816(acc[mi][ni], af[mi], bf[ni >> 1][(ni & 1)], bf[ni >> 1][(ni & 1) + 2]);
        }
    }

    // ---- epilogue ----
    __syncthreads();   // pipe done; reuse smem as v2 tile [64][VPITCH] floats

    const int laneR = lane >> 2;
    const int laneC = (lane & 3) * 2;

    if (wn >= 4) {
        // dump v2 half (global cols 128..255 -> tile cols 0..127)
#pragma unroll
        for (int mi = 0; mi < 2; mi++) {
#pragma unroll
            for (int ni = 0; ni < 4; ni++) {
                int r = wm * 32 + mi * 16 + laneR;
                int c = (wn - 4) * 32 + ni * 8 + laneC;
                uint32_t a0 = sb + (uint32_t)(r * (VPITCH * 4) + c * 4);
                stsf2(a0,                    acc[mi][ni][0], acc[mi][ni][1]);
                stsf2(a0 + 8 * (VPITCH * 4), acc[mi][ni][2], acc[mi][ni][3]);
            }
        }
    }
    __syncthreads();

    if (wn < 4) {
        const float* sV = (const float*)smem;
        const int bidx = blockIdx.x >> 5;   // 32 CTAs per batch
        float gm[4][2];
#pragma unroll
        for (int ni = 0; ni < 4; ni++) {
            const int c = wn * 32 + ni * 8 + laneC;
            const float bb1a = __ldg(&b1[c]),     bb1b = __ldg(&b1[c + 1]);
            const float bb2a = __ldg(&b2[c]),     bb2b = __ldg(&b2[c + 1]);
            float m0 = -INFINITY, m1 = -INFINITY;
#pragma unroll
            for (int mi = 0; mi < 2; mi++) {
                int r0 = wm * 32 + mi * 16 + laneR;
                float v2a0 = sV[r0 * VPITCH + c]           + bb2a;
                float v2b0 = sV[r0 * VPITCH + c + 1]       + bb2b;
                float v2a1 = sV[(r0 + 8) * VPITCH + c]     + bb2a;
                float v2b1 = sV[(r0 + 8) * VPITCH + c + 1] + bb2b;
                float g0 = (acc[mi][ni][0] + bb1a) / (1.0f + __expf(-v2a0));
                float g1 = (acc[mi][ni][1] + bb1b) / (1.0f + __expf(-v2b0));
                float g2 = (acc[mi][ni][2] + bb1a) / (1.0f + __expf(-v2a1));
                float g3 = (acc[mi][ni][3] + bb1b) / (1.0f + __expf(-v2b1));
                m0 = fmaxf(m0, fmaxf(g0, g2));
                m1 = fmaxf(m1, fmaxf(g1, g3));
            }
            gm[ni][0] = m0;
            gm[ni][1] = m1;
        }
#pragma unroll
        for (int ni = 0; ni < 4; ni++) {
#pragma unroll
            for (int off = 4; off < 32; off <<= 1) {
                gm[ni][0] = fmaxf(gm[ni][0], __shfl_xor_sync(0xffffffffu, gm[ni][0], off));
                gm[ni][1] = fmaxf(gm[ni][1], __shfl_xor_sync(0xffffffffu, gm[ni][1], off));
            }
        }
        if (laneR == 0) {
#pragma unroll
            for (int ni = 0; ni < 4; ni++) {
                int c = wn * 32 + ni * 8 + laneC;
                atomicMaxFloat(&out[bidx * C_ + c],     gm[ni][0]);
                atomicMaxFloat(&out[bidx * C_ + c + 1], gm[ni][1]);
            }
        }
    }
}

extern "C" void kernel_launch(void* const* d_in, const int* in_sizes, int n_in,
                              void* d_out, int out_size) {
    const float* z  = (const float*)d_in[0];
    const float* W1 = (const float*)d_in[1];
    const float* b1 = (const float*)d_in[2];
    const float* W2 = (const float*)d_in[3];
    const float* b2 = (const float*)d_in[4];
    float* out = (float*)d_out;
    (void)in_sizes; (void)n_in; (void)out_size;

    cudaFuncSetAttribute(gemm_gate_max, cudaFuncAttributeMaxDynamicSharedMemorySize, SMEMSZ);

    prep_weights<<<(C_ * KW_ + 255) / 256, 256>>>(W1, W2, out);
    gemm_gate_max<<<NCTA, NTH, SMEMSZ>>>(z, b1, b2, out);
}

// round 12
// speedup vs baseline: 1.2511x; 1.2511x over previous
#include <cuda_runtime.h>
#include <cuda_fp16.h>
#include <math.h>
#include <stdint.h>

// ---------------- problem constants ----------------
#define B_   8
#define E_   8
#define C_   128
#define KW_  512
#define Mtot 16384          // B*L
#define KKd  4096           // KW*E
#define NNd  256            // 2*C

// ---------------- GEMM tiling ----------------
#define MT     64           // CTA M tile
#define KC     64           // K chunk (fp16 elems) -> 128B rows (SW128)
#define NCHUNK (KKd / KC)   // 64
#define NTH    256          // 8 warps: 2(M) x 4(N), warp tile 32x64
#define NCTA   (Mtot / MT)  // 256

// smem (bytes), SW128 swizzled 128B rows
#define ROWB    128
#define A_STG   (64 * ROWB)          // 8192 per stage  (2 stages)
#define B_STG   (256 * ROWB)         // 32768 per stage (3 stages)
#define SM_A    0
#define SM_B    (2 * A_STG)          // 16384
#define SMEMSZ  (SM_B + 3 * B_STG)   // 114688 -> 2 CTAs = 224KB/SM
#define VPITCH  132                  // epilogue overlay [64][132] f32 = 33792B

#define BROW32  (32 * KKd)           // 32 B-rows in HALVES = 131072

// fp16 weights, [n][kk] K-major; n<128 -> W1, n>=128 -> W2
__device__ __half g_Bh[(size_t)NNd * KKd];

// ---------------- helpers ----------------
__device__ __forceinline__ uint32_t smem_u32(const void* p) {
    uint32_t a;
    asm("{ .reg .u64 t; cvta.to.shared.u64 t, %1; cvt.u32.u64 %0, t; }" : "=r"(a) : "l"(p));
    return a;
}
__device__ __forceinline__ uint32_t pack_h2(float x, float y) {
    __half2 t = __floats2half2_rn(x, y);
    return *reinterpret_cast<uint32_t*>(&t);
}
__device__ __forceinline__ void ldmx4(uint32_t* r, uint32_t addr) {
    asm volatile("ldmatrix.sync.aligned.m8n8.x4.shared.b16 {%0,%1,%2,%3}, [%4];"
                 : "=r"(r[0]), "=r"(r[1]), "=r"(r[2]), "=r"(r[3]) : "r"(addr));
}
__device__ __forceinline__ void mma16816(float* d, const uint32_t* a, uint32_t b0, uint32_t b1) {
    asm volatile("mma.sync.aligned.m16n8k16.row.col.f32.f16.f16.f32 "
                 "{%0,%1,%2,%3}, {%4,%5,%6,%7}, {%8,%9}, {%0,%1,%2,%3};"
                 : "+f"(d[0]), "+f"(d[1]), "+f"(d[2]), "+f"(d[3])
                 : "r"(a[0]), "r"(a[1]), "r"(a[2]), "r"(a[3]), "r"(b0), "r"(b1));
}
__device__ __forceinline__ void sts64(uint32_t a, uint32_t x, uint32_t y) {
    asm volatile("st.shared.v2.b32 [%0], {%1,%2};" :: "r"(a), "r"(x), "r"(y) : "memory");
}
__device__ __forceinline__ void stsf2(uint32_t a, float x, float y) {
    asm volatile("st.shared.v2.f32 [%0], {%1,%2};" :: "r"(a), "f"(x), "f"(y) : "memory");
}
__device__ __forceinline__ void cpasync16(uint32_t dst, const void* src) {
    asm volatile("cp.async.cg.shared.global [%0], [%1], 16;" :: "r"(dst), "l"(src) : "memory");
}
__device__ __forceinline__ void cp_commit() { asm volatile("cp.async.commit_group;" ::: "memory"); }
__device__ __forceinline__ void cp_wait1() { asm volatile("cp.async.wait_group 1;" ::: "memory"); }
__device__ __forceinline__ void atomicMaxFloat(float* addr, float val) {
    if (val >= 0.0f) atomicMax((int*)addr, __float_as_int(val));
    else             atomicMin((unsigned int*)addr, __float_as_uint(val));
}

// ---------------- prep: weights -> fp16 [n][kk], coalesced; also init out ----------------
__global__ void prep_weights(const float* __restrict__ W1, const float* __restrict__ W2,
                             float* __restrict__ out) {
    int idx = blockIdx.x * blockDim.x + threadIdx.x;   // over C_*KW_ = 65536
    if (idx < B_ * C_) out[idx] = -INFINITY;
    if (idx >= C_ * KW_) return;
    int c = idx / KW_;
    int k = idx % KW_;
    uint32_t p1[4], p2[4];
#pragma unroll
    for (int e2 = 0; e2 < 4; e2++) {
        float a0 = W1[((size_t)c * E_ + 2 * e2) * KW_ + k];
        float a1 = W1[((size_t)c * E_ + 2 * e2 + 1) * KW_ + k];
        p1[e2] = pack_h2(a0, a1);
        float b0 = W2[((size_t)c * E_ + 2 * e2) * KW_ + k];
        float b1v = W2[((size_t)c * E_ + 2 * e2 + 1) * KW_ + k];
        p2[e2] = pack_h2(b0, b1v);
    }
    *(uint4*)&g_Bh[(size_t)c * KKd + k * E_]        = make_uint4(p1[0], p1[1], p1[2], p1[3]);
    *(uint4*)&g_Bh[(size_t)(C_ + c) * KKd + k * E_] = make_uint4(p2[0], p2[1], p2[2], p2[3]);
}

// ---------------- main fused GEMM + gate + max ----------------
__global__ __launch_bounds__(NTH, 2)
void gemm_gate_max(const float* __restrict__ Z,
                   const float* __restrict__ b1,
                   const float* __restrict__ b2,
                   float* __restrict__ out) {
    extern __shared__ char smem[];
    const uint32_t sb = smem_u32(smem);
    const int tid  = threadIdx.x;
    const int wid  = tid >> 5;
    const int lane = tid & 31;
    const int wm   = wid & 1;        // M group (0..1), 32 rows each
    const int wn   = wid >> 1;       // N group (0..3), 64 cols each
    const int m_base = blockIdx.x * MT;

    // ---- staging mappings (SW128 swizzle: col ^= (row&7)<<4) ----
    const int aRow0 = tid >> 3;                 // 0..31
    const int aU    = tid & 7;
    const float* aSrc0 = Z + (size_t)(m_base + aRow0) * KKd + aU * 8;   // +q*32 rows
    const uint32_t aDst0 = (uint32_t)(aRow0 * ROWB + ((aU << 4) ^ ((aRow0 & 7) << 4)));
    const __half* bSrc0 = g_Bh + (size_t)(tid >> 3) * KKd + aU * 8;     // +q*BROW32 halves
    const uint32_t bDst0 = (uint32_t)((tid >> 3) * ROWB + ((aU << 4) ^ (((tid >> 3) & 7) << 4)));

    // ---- fragment base addresses (stage 0), per-slice addr = base ^ (ks*32) ----
    const uint32_t laneXor = (uint32_t)((lane & 7) << 4);
    const uint32_t fragCol = (uint32_t)(((lane >> 4) << 4)) ^ laneXor;
    const uint32_t aFragB  = sb + SM_A + (uint32_t)((wm * 32 + (lane & 15)) * ROWB) + fragCol;
    const uint32_t bFragB  = sb + SM_B + (uint32_t)((wn * 64 + (lane & 15)) * ROWB) + fragCol;

    float acc[2][8][4];
#pragma unroll
    for (int mi = 0; mi < 2; mi++)
#pragma unroll
        for (int ni = 0; ni < 8; ni++)
#pragma unroll
            for (int q = 0; q < 4; q++) acc[mi][ni][q] = 0.0f;

    uint32_t pA[8];   // packed fp16 A prefetch: 2 granules x 4 regs

    // ---- prologue: B(0), B(1) via cp.async (2 groups); A(0) STS; pA <- A(1) ----
#pragma unroll
    for (int s = 0; s < 2; s++) {
#pragma unroll
        for (int q = 0; q < 8; q++)
            cpasync16(sb + SM_B + s * B_STG + bDst0 + q * 4096,
                      bSrc0 + (size_t)q * BROW32 + s * KC);
        cp_commit();
    }
#pragma unroll
    for (int q = 0; q < 2; q++) {
        float4 v0 = *(const float4*)(aSrc0 + (size_t)q * 32 * KKd);
        float4 v1 = *(const float4*)(aSrc0 + (size_t)q * 32 * KKd + 4);
        sts64(sb + SM_A + aDst0 + q * 4096, pack_h2(v0.x, v0.y), pack_h2(v0.z, v0.w));
        sts64(sb + SM_A + aDst0 + q * 4096 + 8, pack_h2(v1.x, v1.y), pack_h2(v1.z, v1.w));
    }
#pragma unroll
    for (int q = 0; q < 2; q++) {
        float4 v0 = *(const float4*)(aSrc0 + (size_t)q * 32 * KKd + KC);
        float4 v1 = *(const float4*)(aSrc0 + (size_t)q * 32 * KKd + KC + 4);
        pA[4 * q]     = pack_h2(v0.x, v0.y);
        pA[4 * q + 1] = pack_h2(v0.z, v0.w);
        pA[4 * q + 2] = pack_h2(v1.x, v1.y);
        pA[4 * q + 3] = pack_h2(v1.z, v1.w);
    }

    int bStage = 0;   // j % 3
    for (int j = 0; j < NCHUNK; ++j) {
        cp_wait1();        // group j complete (one group committed per iter + 2 prologue)
        __syncthreads();   // publish B(j), A(j); all reads of overwrite targets are done

        // ---- issue B(j+2) into stage (j+2)%3 ----
        if (j + 2 < NCHUNK) {
            const int wstage = (bStage + 2 >= 3) ? bStage - 1 : bStage + 2;
            const uint32_t bb = sb + SM_B + (uint32_t)wstage * B_STG;
#pragma unroll
            for (int q = 0; q < 8; q++)
                cpasync16(bb + bDst0 + q * 4096, bSrc0 + (size_t)q * BROW32 + (j + 2) * KC);
        }
        cp_commit();       // always one group per iter (may be empty)

        // ---- STS A(j+1) into stage (j+1)&1; LDG A(j+2) ----
        if (j + 1 < NCHUNK) {
            const uint32_t aa = sb + SM_A + (uint32_t)((j + 1) & 1) * A_STG;
            sts64(aa + aDst0,            pA[0], pA[1]);
            sts64(aa + aDst0 + 8,        pA[2], pA[3]);
            sts64(aa + aDst0 + 4096,     pA[4], pA[5]);
            sts64(aa + aDst0 + 4096 + 8, pA[6], pA[7]);
        }
        if (j + 2 < NCHUNK) {
#pragma unroll
            for (int q = 0; q < 2; q++) {
                float4 v0 = *(const float4*)(aSrc0 + (size_t)q * 32 * KKd + (j + 2) * KC);
                float4 v1 = *(const float4*)(aSrc0 + (size_t)q * 32 * KKd + (j + 2) * KC + 4);
                pA[4 * q]     = pack_h2(v0.x, v0.y);
                pA[4 * q + 1] = pack_h2(v0.z, v0.w);
                pA[4 * q + 2] = pack_h2(v1.x, v1.y);
                pA[4 * q + 3] = pack_h2(v1.z, v1.w);
            }
        }

        // ---- compute chunk j: 4 k16 slices ----
        const uint32_t sA = aFragB + (uint32_t)(j & 1) * A_STG;
        const uint32_t sB = bFragB + (uint32_t)bStage * B_STG;
#pragma unroll
        for (int ks = 0; ks < 4; ks++) {
            const uint32_t ko = (uint32_t)(ks * 32);
            uint32_t af[2][4], bf[4][4];
#pragma unroll
            for (int mi = 0; mi < 2; mi++)
                ldmx4(af[mi], (sA + mi * (16 * ROWB)) ^ ko);
#pragma unroll
            for (int n2 = 0; n2 < 4; n2++)
                ldmx4(bf[n2], (sB + n2 * (16 * ROWB)) ^ ko);
#pragma unroll
            for (int mi = 0; mi < 2; mi++)
#pragma unroll
                for (int ni = 0; ni < 8; ni++)
                    mma16816(acc[mi][ni], af[mi], bf[ni >> 1][(ni & 1)], bf[ni >> 1][(ni & 1) + 2]);
        }

        bStage = (bStage == 2) ? 0 : bStage + 1;
    }

    // ---- epilogue ----
    __syncthreads();   // pipe done; reuse smem as v2 tile [64][VPITCH] floats

    const int laneR = lane >> 2;
    const int laneC = (lane & 3) * 2;

    if (wn >= 2) {
#pragma unroll
        for (int mi = 0; mi < 2; mi++) {
#pragma unroll
            for (int ni = 0; ni < 8; ni++) {
                int r = wm * 32 + mi * 16 + laneR;
                int c = (wn - 2) * 64 + ni * 8 + laneC;
                uint32_t a0 = sb + (uint32_t)(r * (VPITCH * 4) + c * 4);
                stsf2(a0,                    acc[mi][ni][0], acc[mi][ni][1]);
                stsf2(a0 + 8 * (VPITCH * 4), acc[mi][ni][2], acc[mi][ni][3]);
            }
        }
    }
    __syncthreads();

    if (wn < 2) {
        const float* sV = (const float*)smem;
        const int bidx = blockIdx.x >> 5;   // 32 CTAs per batch
        float gm[8][2];
#pragma unroll
        for (int ni = 0; ni < 8; ni++) {
            const int c = wn * 64 + ni * 8 + laneC;
            const float bb1a = __ldg(&b1[c]),     bb1b = __ldg(&b1[c + 1]);
            const float bb2a = __ldg(&b2[c]),     bb2b = __ldg(&b2[c + 1]);
            float m0 = -INFINITY, m1 = -INFINITY;
#pragma unroll
            for (int mi = 0; mi < 2; mi++) {
                int r0 = wm * 32 + mi * 16 + laneR;
                float v2a0 = sV[r0 * VPITCH + c]           + bb2a;
                float v2b0 = sV[r0 * VPITCH + c + 1]       + bb2b;
                float v2a1 = sV[(r0 + 8) * VPITCH + c]     + bb2a;
                float v2b1 = sV[(r0 + 8) * VPITCH + c + 1] + bb2b;
                float g0 = (acc[mi][ni][0] + bb1a) / (1.0f + __expf(-v2a0));
                float g1 = (acc[mi][ni][1] + bb1b) / (1.0f + __expf(-v2b0));
                float g2 = (acc[mi][ni][2] + bb1a) / (1.0f + __expf(-v2a1));
                float g3 = (acc[mi][ni][3] + bb1b) / (1.0f + __expf(-v2b1));
                m0 = fmaxf(m0, fmaxf(g0, g2));
                m1 = fmaxf(m1, fmaxf(g1, g3));
            }
            gm[ni][0] = m0;
            gm[ni][1] = m1;
        }
#pragma unroll
        for (int ni = 0; ni < 8; ni++) {
#pragma unroll
            for (int off = 4; off < 32; off <<= 1) {
                gm[ni][0] = fmaxf(gm[ni][0], __shfl_xor_sync(0xffffffffu, gm[ni][0], off));
                gm[ni][1] = fmaxf(gm[ni][1], __shfl_xor_sync(0xffffffffu, gm[ni][1], off));
            }
        }
        if (laneR == 0) {
#pragma unroll
            for (int ni = 0; ni < 8; ni++) {
                int c = wn * 64 + ni * 8 + laneC;
                atomicMaxFloat(&out[bidx * C_ + c],     gm[ni][0]);
                atomicMaxFloat(&out[bidx * C_ + c + 1], gm[ni][1]);
            }
        }
    }
}

extern "C" void kernel_launch(void* const* d_in, const int* in_sizes, int n_in,
                              void* d_out, int out_size) {
    const float* z  = (const float*)d_in[0];
    const float* W1 = (const float*)d_in[1];
    const float* b1 = (const float*)d_in[2];
    const float* W2 = (const float*)d_in[3];
    const float* b2 = (const float*)d_in[4];
    float* out = (float*)d_out;
    (void)in_sizes; (void)n_in; (void)out_size;

    cudaFuncSetAttribute(gemm_gate_max, cudaFuncAttributeMaxDynamicSharedMemorySize, SMEMSZ);

    prep_weights<<<(C_ * KW_ + 255) / 256, 256>>>(W1, W2, out);
    gemm_gate_max<<<NCTA, NTH, SMEMSZ>>>(z, b1, b2, out);
}